// round 11
// baseline (speedup 1.0000x reference)
#include <cuda_runtime.h>
#include <cuda_bf16.h>

// QuantumLinear: B=4096, IN_F=1024, NQ=4, L=2, C=256 circuits.
// Closed-form <Z_q> via Heisenberg propagation (exact):
//   alpha_q = x_q + w[c,0,q], beta_q = w[c,1,q]
//   <Z0> = C1C3*(a0*C0 + a3*S0) + S1S3*(a1*S0 + a2*C0)
//   <Z1> = C3*(c0c1*C0C2 + s0s1*S0S2)
//   <Z2> = c0c1c2*C1C3 + c0s1s2*S1S3
//   <Z3> = C2*(e0*C0 + e1*S0) + S2*(e2*C0 + e3*S0)
// R10: uniform persistent grid — 592 CTAs = exactly 4 per SM, single wave,
// no CTA-count quantization (R2's grid=512 left 52 SMs with 4 CTAs vs 96
// with 3 => 33% imbalance). Each CTA grid-strides rows (6-7 rows), prologue
// amortized once per CTA, depth-1 prefetch on the next row.

static constexpr int NCIRC = 256;
static constexpr int GRID  = 592;     // 4 CTAs x 148 SMs, uniform residency
static constexpr int BROWS = 4096;    // batch rows

__global__ void __launch_bounds__(NCIRC) qfused_kernel(
    const float4* __restrict__ x,     // (B*256) float4
    const float4* __restrict__ w4,    // (256*2) float4  = weights (256,2,4)
    float4* __restrict__ out)         // (B*256) float4
{
    const int c = threadIdx.x;                 // circuit 0..255

    // first row's load + weight loads issued before prologue math
    int row = blockIdx.x;
    float4 cur = x[row * NCIRC + c];
    const float4 w0 = w4[c * 2 + 0];           // alpha offsets
    const float4 w1 = w4[c * 2 + 1];           // beta angles

    // ---- per-circuit coefficients (overlap the loads above) ----
    float cb0, sb0, cb1, sb1, cb2, sb2, cb3, sb3;
    __sincosf(w1.x, &sb0, &cb0);
    __sincosf(w1.y, &sb1, &cb1);
    __sincosf(w1.z, &sb2, &cb2);
    __sincosf(w1.w, &sb3, &cb3);

    const float c1c2 = cb1 * cb2;
    const float s1s2 = sb1 * sb2;
    const float a0 = c1c2 * cb3, a1 = c1c2 * sb3;
    const float a2 = s1s2 * cb3, a3 = s1s2 * sb3;
    const float p0 = cb0 * cb1,  p1 = sb0 * sb1;
    const float d0 = cb0 * c1c2, d1 = cb0 * s1s2;
    const float e0 = cb0 * c1c2 * cb3;
    const float e1 = cb0 * s1s2 * sb3;
    const float e2 = sb0 * cb1 * sb2 * sb3;
    const float e3 = sb0 * sb1 * cb2 * cb3;

    // ---- persistent row loop: prefetch row+GRID while computing row ----
    for (;;) {
        const int nrow = row + GRID;
        const bool more = (nrow < BROWS);
        float4 nxt;
        if (more) nxt = x[nrow * NCIRC + c];

        float S0, C0, S1, C1, S2, C2, S3, C3;
        __sincosf(cur.x + w0.x, &S0, &C0);
        __sincosf(cur.y + w0.y, &S1, &C1);
        __sincosf(cur.z + w0.z, &S2, &C2);
        __sincosf(cur.w + w0.w, &S3, &C3);

        const float C1C3 = C1 * C3;
        const float S1S3 = S1 * S3;
        const float C0C2 = C0 * C2;
        const float S0S2 = S0 * S2;

        float4 z;
        z.x = fmaf(C1C3, fmaf(a0, C0, a3 * S0), S1S3 * fmaf(a1, S0, a2 * C0));
        z.y = C3 * fmaf(p0, C0C2, p1 * S0S2);
        z.z = fmaf(d0, C1C3, d1 * S1S3);
        z.w = fmaf(C2, fmaf(e0, C0, e1 * S0), S2 * fmaf(e2, C0, e3 * S0));

        out[row * NCIRC + c] = z;

        if (!more) break;
        cur = nxt;
        row = nrow;
    }
}

extern "C" void kernel_launch(void* const* d_in, const int* in_sizes, int n_in,
                              void* d_out, int out_size) {
    const float* x = (const float*)d_in[0];       // (4096, 1024) f32
    const float* w = (const float*)d_in[1];       // (256, 2, 4)  f32
    float* out = (float*)d_out;                   // (4096, 1024) f32

    qfused_kernel<<<GRID, NCIRC>>>(
        (const float4*)x, (const float4*)w, (float4*)out);
}

// round 13
// speedup vs baseline: 1.2399x; 1.2399x over previous
#include <cuda_runtime.h>
#include <cuda_bf16.h>

// QuantumLinear: B=4096, IN_F=1024, NQ=4, L=2, C=256 circuits.
// Closed-form <Z_q> via Heisenberg propagation (exact):
//   alpha_q = x_q + w[c,0,q], beta_q = w[c,1,q]
// R11: ILP restructure. Same shape as the 7.9us best (ROWS=8, grid=512,
// block=256) but: (a) reg budget raised to ~84 via launch_bounds(256,3),
// (b) all 8 x-row loads front-batched (MLP=8), (c) software-pipelined
// compute with double-buffered sin/cos registers so row r+1's 8 MUFUs
// stream on the XU pipe while row r's FMA tail runs on the FMA pipe.

static constexpr int NCIRC = 256;
static constexpr int ROWS  = 8;     // batch rows per thread

__global__ void __launch_bounds__(NCIRC, 3) qfused_kernel(
    const float4* __restrict__ x,     // (B*256) float4
    const float4* __restrict__ w4,    // (256*2) float4  = weights (256,2,4)
    float4* __restrict__ out)         // (B*256) float4
{
    const int c = threadIdx.x;                 // circuit 0..255
    const int base = (blockIdx.x * ROWS) * NCIRC + c;

    // ---- front-batch all loads: 8 x rows + 2 weight vectors (MLP=10) ----
    float4 xv[ROWS];
#pragma unroll
    for (int r = 0; r < ROWS; r++)
        xv[r] = x[base + r * NCIRC];
    const float4 w0 = w4[c * 2 + 0];           // alpha offsets
    const float4 w1 = w4[c * 2 + 1];           // beta angles

    // ---- per-circuit coefficients (overlaps the loads) ----
    float cb0, sb0, cb1, sb1, cb2, sb2, cb3, sb3;
    __sincosf(w1.x, &sb0, &cb0);
    __sincosf(w1.y, &sb1, &cb1);
    __sincosf(w1.z, &sb2, &cb2);
    __sincosf(w1.w, &sb3, &cb3);

    const float c1c2 = cb1 * cb2;
    const float s1s2 = sb1 * sb2;
    const float a0 = c1c2 * cb3, a1 = c1c2 * sb3;
    const float a2 = s1s2 * cb3, a3 = s1s2 * sb3;
    const float p0 = cb0 * cb1,  p1 = sb0 * sb1;
    const float d0 = cb0 * c1c2, d1 = cb0 * s1s2;
    const float e0 = cb0 * c1c2 * cb3;
    const float e1 = cb0 * s1s2 * sb3;
    const float e2 = sb0 * cb1 * sb2 * sb3;
    const float e3 = sb0 * sb1 * cb2 * cb3;

    // ---- software-pipelined compute: trig of row r+1 overlaps FMA of row r ----
    float S[2][4], C[2][4];

    __sincosf(xv[0].x + w0.x, &S[0][0], &C[0][0]);
    __sincosf(xv[0].y + w0.y, &S[0][1], &C[0][1]);
    __sincosf(xv[0].z + w0.z, &S[0][2], &C[0][2]);
    __sincosf(xv[0].w + w0.w, &S[0][3], &C[0][3]);

#pragma unroll
    for (int r = 0; r < ROWS; r++) {
        const int cur = r & 1, nxt = cur ^ 1;
        if (r + 1 < ROWS) {
            __sincosf(xv[r + 1].x + w0.x, &S[nxt][0], &C[nxt][0]);
            __sincosf(xv[r + 1].y + w0.y, &S[nxt][1], &C[nxt][1]);
            __sincosf(xv[r + 1].z + w0.z, &S[nxt][2], &C[nxt][2]);
            __sincosf(xv[r + 1].w + w0.w, &S[nxt][3], &C[nxt][3]);
        }

        const float S0 = S[cur][0], C0 = C[cur][0];
        const float S1 = S[cur][1], C1 = C[cur][1];
        const float S2 = S[cur][2], C2 = C[cur][2];
        const float S3 = S[cur][3], C3 = C[cur][3];

        const float C1C3 = C1 * C3;
        const float S1S3 = S1 * S3;
        const float C0C2 = C0 * C2;
        const float S0S2 = S0 * S2;

        float4 z;
        z.x = fmaf(C1C3, fmaf(a0, C0, a3 * S0), S1S3 * fmaf(a1, S0, a2 * C0));
        z.y = C3 * fmaf(p0, C0C2, p1 * S0S2);
        z.z = fmaf(d0, C1C3, d1 * S1S3);
        z.w = fmaf(C2, fmaf(e0, C0, e1 * S0), S2 * fmaf(e2, C0, e3 * S0));

        out[base + r * NCIRC] = z;
    }
}

extern "C" void kernel_launch(void* const* d_in, const int* in_sizes, int n_in,
                              void* d_out, int out_size) {
    const float* x = (const float*)d_in[0];       // (4096, 1024) f32
    const float* w = (const float*)d_in[1];       // (256, 2, 4)  f32
    float* out = (float*)d_out;                   // (4096, 1024) f32

    const int B = 4096;
    qfused_kernel<<<B / ROWS, NCIRC>>>(
        (const float4*)x, (const float4*)w, (float4*)out);
}